// round 15
// baseline (speedup 1.0000x reference)
#include <cuda_runtime.h>
#include <cuda_bf16.h>
#include <math.h>
#include <stdint.h>

#define NN   8192
#define DIN  512
#define DD   64

// ===========================================================================
// Device globals (no allocation allowed).
// ===========================================================================
__device__ __nv_bfloat16  g_khhi[NN * DD];
__device__ __nv_bfloat16  g_khlo[NN * DD];
__device__ __nv_bfloat16  g_vhhi[NN * DD];
__device__ __nv_bfloat16  g_vhlo[NN * DD];
__device__ float          g_norm[NN];
__device__ unsigned       g_maxnorm_bits;   // reset in prep CTA0; atomicMax after
__device__ unsigned       g_mask[NN * (NN / 32)];   // 8MB bitmask

// ===========================================================================
// Helpers
// ===========================================================================
__device__ __forceinline__ uint32_t smem_u32(const void* p) {
    uint32_t a;
    asm("{ .reg .u64 t; cvta.to.shared.u64 t, %1; cvt.u32.u64 %0, t; }"
        : "=r"(a) : "l"(p));
    return a;
}
#define SW128(x) ((uint32_t)(x) ^ ((((uint32_t)(x)) >> 3) & 0x70))

__device__ __forceinline__ void mma16816(float* d,
    uint32_t a0, uint32_t a1, uint32_t a2, uint32_t a3,
    uint32_t b0, uint32_t b1) {
    asm volatile(
        "mma.sync.aligned.m16n8k16.row.col.f32.bf16.bf16.f32 "
        "{%0,%1,%2,%3},{%4,%5,%6,%7},{%8,%9},{%0,%1,%2,%3};"
        : "+f"(d[0]), "+f"(d[1]), "+f"(d[2]), "+f"(d[3])
        : "r"(a0), "r"(a1), "r"(a2), "r"(a3), "r"(b0), "r"(b1));
}
#define LDSM4(r0, r1, r2, r3, a)                                        \
    asm volatile("ldmatrix.sync.aligned.m8n8.x4.shared.b16 "            \
                 "{%0,%1,%2,%3}, [%4];"                                 \
                 : "=r"(r0), "=r"(r1), "=r"(r2), "=r"(r3) : "r"(a))
#define LDSM4T(r0, r1, r2, r3, a)                                       \
    asm volatile("ldmatrix.sync.aligned.m8n8.x4.trans.shared.b16 "      \
                 "{%0,%1,%2,%3}, [%4];"                                 \
                 : "=r"(r0), "=r"(r1), "=r"(r2), "=r"(r3) : "r"(a))
#define CP16(dst, src)                                                  \
    asm volatile("cp.async.cg.shared.global [%0], [%1], 16;"            \
                 :: "r"(dst), "l"(src))
#define CP_COMMIT() asm volatile("cp.async.commit_group;" ::: "memory")
#define BAR_GRP(id) asm volatile("bar.sync %0, 128;" :: "r"(id) : "memory")

__device__ __forceinline__ float ex2f(float x) {
    float r;
    asm("ex2.approx.ftz.f32 %0, %1;" : "=f"(r) : "f"(x));
    return r;
}

// Pack p0 (lo) / p1 (hi) into bf16x2 hi-part + exact fp32 residual bf16x2.
__device__ __forceinline__ void packbf(float p0, float p1,
                                       uint32_t& hv, uint32_t& rv) {
    asm("cvt.rn.bf16x2.f32 %0, %1, %2;" : "=r"(hv) : "f"(p1), "f"(p0));
    float h0 = __uint_as_float(hv << 16);
    float h1 = __uint_as_float(hv & 0xFFFF0000u);
    asm("cvt.rn.bf16x2.f32 %0, %1, %2;" : "=r"(rv) : "f"(p1 - h1), "f"(p0 - h0));
}

// ===========================================================================
// Stage 1: ONE heterogeneous launch (round-12 proven version).
//   blockIdx < 128   : projection CTAs (FMA-bound) + fused row norms
//   blockIdx >= 128  : 2048 mask-packing CTAs (DRAM-bound streaming)
// ===========================================================================
#define PROJ_CTAS 128
#define MASK_CTAS 2048

__global__ void __launch_bounds__(256) prep_kernel(const float* __restrict__ inp,
                                                   const float* __restrict__ kW,
                                                   const float* __restrict__ vW,
                                                   const int* __restrict__ adj) {
    const int tid = threadIdx.x;

    if (blockIdx.x >= PROJ_CTAS) {
        // ---- mask role: warp packs 128 consecutive 32-key words, MLP=16.
        const int warp = ((blockIdx.x - PROJ_CTAS) * 256 + tid) >> 5;
        const int lane = tid & 31;
        const long base = (long)warp * 128;
        for (int i0 = 0; i0 < 128; i0 += 16) {
            int v[16];
            #pragma unroll
            for (int u = 0; u < 16; u++)
                v[u] = adj[(base + i0 + u) * 32 + lane];
            #pragma unroll
            for (int u = 0; u < 16; u++) {
                unsigned b = __ballot_sync(0xffffffffu, v[u] > 0);
                if (lane == 0) g_mask[base + i0 + u] = b;
            }
        }
        return;
    }

    // ---- projection role (FFMA, fused bf16 splits + norms).
    __shared__ float sIn[64][36];
    __shared__ float sKW[32][65];
    __shared__ float sVW[32][65];
    const int tx = tid & 15, ty = tid >> 4;
    if (blockIdx.x == 0 && tid == 0) g_maxnorm_bits = 0u;
    const int rbase = blockIdx.x * 64;
    float ak[4][4] = {}, av[4][4] = {};

    for (int kc = 0; kc < DIN; kc += 32) {
        __syncthreads();
        for (int e = tid; e < 64 * 32; e += 256) {
            int r = e >> 5, c = e & 31;
            sIn[r][c] = inp[(rbase + r) * DIN + kc + c];
        }
        for (int e = tid; e < 32 * 64; e += 256) {
            int r = e >> 6, c = e & 63;
            sKW[r][c] = kW[(kc + r) * DD + c];
            sVW[r][c] = vW[(kc + r) * DD + c];
        }
        __syncthreads();
        #pragma unroll 8
        for (int kk = 0; kk < 32; kk++) {
            float a[4], bk[4], bv[4];
            #pragma unroll
            for (int i = 0; i < 4; i++) a[i] = sIn[ty + 16 * i][kk];
            #pragma unroll
            for (int j = 0; j < 4; j++) { bk[j] = sKW[kk][tx + 16 * j];
                                          bv[j] = sVW[kk][tx + 16 * j]; }
            #pragma unroll
            for (int i = 0; i < 4; i++)
                #pragma unroll
                for (int j = 0; j < 4; j++) {
                    ak[i][j] = fmaf(a[i], bk[j], ak[i][j]);
                    av[i][j] = fmaf(a[i], bv[j], av[i][j]);
                }
        }
    }

    #pragma unroll
    for (int i = 0; i < 4; i++) {
        float part = 0.f;
        #pragma unroll
        for (int j = 0; j < 4; j++) {
            int idx = (rbase + ty + 16 * i) * DD + tx + 16 * j;
            float kv = ak[i][j], vv = av[i][j];
            part = fmaf(kv, kv, part);
            __nv_bfloat16 kh = __float2bfloat16(kv);
            g_khhi[idx] = kh;
            g_khlo[idx] = __float2bfloat16(kv - __bfloat162float(kh));
            __nv_bfloat16 vh = __float2bfloat16(vv);
            g_vhhi[idx] = vh;
            g_vhlo[idx] = __float2bfloat16(vv - __bfloat162float(vh));
        }
        #pragma unroll
        for (int off = 1; off < 16; off <<= 1)
            part += __shfl_xor_sync(0xffffffffu, part, off);
        if (tx == 0) {
            float n = sqrtf(part);
            g_norm[rbase + ty + 16 * i] = n;
            atomicMax(&g_maxnorm_bits, __float_as_uint(n));
        }
    }
}

// ===========================================================================
// Stage 2: HMMA flash attention, fixed per-row max.
// grid = 128 (64 q rows / CTA), 512 threads (16 warps).
// warp w: q-band (w&3)*16, key quarter wh=(w>>2)*32.
// Per-group pipelines (named barriers) + SPLIT S ACCUMULATOR CHAINS:
// hi-pass into sh (chain 4), corrections into scr (chain 8) — 4 independent
// HMMA chains per warp in the S phase instead of 2 (chain 12).
// ===========================================================================
#define GSLOT 16384                  // per-group slot: Kq hi/lo + Vq hi/lo
#define GOFF_KHI 0
#define GOFF_KLO 4096
#define GOFF_VHI 8192
#define GOFF_VLO 12288
#define NSLOTS 3
#define GRP_BYTES (NSLOTS * GSLOT)   // 48KB per group
#define SMEM_ATTN (4 * GRP_BYTES)    // 192KB
#define TILES (NN / 128)

// Fill this group's 32-key quarter of tile with keys [kq, kq+32).
__device__ __forceinline__ void fill_quarter(uint32_t gslot, int kq, int ltid) {
    #pragma unroll
    for (int i = 0; i < 2; i++) {
        int e = i * 128 + ltid;      // 256 16B units per array
        int r = e >> 3, b = e & 7;
        uint32_t sw = SW128(r * 128 + b * 16);
        long src = (long)(kq + r) * DD + b * 8;
        CP16(gslot + GOFF_KHI + sw, g_khhi + src);
        CP16(gslot + GOFF_KLO + sw, g_khlo + src);
        CP16(gslot + GOFF_VHI + sw, g_vhhi + src);
        CP16(gslot + GOFF_VLO + sw, g_vhlo + src);
    }
}

__global__ void __launch_bounds__(512, 1)
attn_kernel(float* __restrict__ out) {
    extern __shared__ char smem[];
    const uint32_t sb = smem_u32(smem);
    const int tid  = threadIdx.x;
    const int w    = tid >> 5;
    const int lane = tid & 31;
    const int wq   = w & 3;              // q band
    const int wh   = w >> 2;             // key quarter (0..3) == group
    const int ltid = tid & 127;          // thread id within group
    const int g    = lane >> 2;
    const int tg   = lane & 3;
    const int q0   = wq * 16;
    const int qbase = blockIdx.x * 64;
    const uint32_t gbase = sb + wh * GRP_BYTES;

    // ---- Stage Q at sb (hi) / sb+8192 (lo), extract A fragments.
    {
        int e = tid;                     // 512 16B units
        int r = e >> 3, b = e & 7;
        uint32_t sw = SW128(r * 128 + b * 16);
        *(uint4*)(smem + sw) =
            *(const uint4*)(g_khhi + (qbase + r) * DD + b * 8);
        *(uint4*)(smem + 8192 + sw) =
            *(const uint4*)(g_khlo + (qbase + r) * DD + b * 8);
    }
    __syncthreads();

    uint32_t qh[16], ql[16];
    {
        int arow = q0 + ((lane >> 3) & 1) * 8 + (lane & 7);
        int acol0 = (lane >> 4) * 8;
        #pragma unroll
        for (int ks = 0; ks < 4; ks++) {
            uint32_t sw = SW128(arow * 128 + (ks * 16 + acol0) * 2);
            LDSM4(qh[4*ks], qh[4*ks+1], qh[4*ks+2], qh[4*ks+3], sb + sw);
            LDSM4(ql[4*ks], ql[4*ks+1], ql[4*ks+2], ql[4*ks+3], sb + 8192 + sw);
        }
    }
    __syncthreads();   // Q region free (overlaps group 0 slots)

    // Prologue fills for tiles 0 and 1 (this group's quarters).
    fill_quarter(gbase + 0 * GSLOT, 0 * 128 + wh * 32, ltid);
    CP_COMMIT();
    fill_quarter(gbase + 1 * GSLOT, 1 * 128 + wh * 32, ltid);
    CP_COMMIT();

    // exp in log2 domain: p = 2^(s*c - m').
    const float C_LOG2E = 1.4426950408889634f;
    const float sc = 0.125f * C_LOG2E;
    const float maxn = __uint_as_float(g_maxnorm_bits) * 0.125f * 1.0001f * C_LOG2E;
    const float mq0 = g_norm[qbase + q0 + g] * maxn;
    const float mq1 = g_norm[qbase + q0 + g + 8] * maxn;
    const unsigned* mrow0 = g_mask + (long)(qbase + q0 + g) * (NN / 32) + wh;
    const unsigned* mrow1 = g_mask + (long)(qbase + q0 + g + 8) * (NN / 32) + wh;

    float o[8][4];
    #pragma unroll
    for (int i = 0; i < 8; i++)
        #pragma unroll
        for (int j = 0; j < 4; j++) o[i][j] = 0.f;
    float l0 = 0.f, l1 = 0.f;

    const int krow_l = (lane >> 4) * 8 + (lane & 7);
    const int kcol_l = ((lane >> 3) & 1) * 8;
    const int vrow_l = ((lane >> 3) & 1) * 8 + (lane & 7);
    const int vcol_l = (lane >> 4) * 8;

    for (int t = 0; t < TILES; t++) {
        const uint32_t tbase = gbase + (t % NSLOTS) * GSLOT;

        unsigned mw0 = mrow0[t * 4];
        unsigned mw1 = mrow1[t * 4];

        // wait for this group's tile-t fill, sync the group only.
        if (t + 1 < TILES) asm volatile("cp.async.wait_group 1;" ::: "memory");
        else               asm volatile("cp.async.wait_group 0;" ::: "memory");
        BAR_GRP(wh + 1);

        if (t + 2 < TILES) {
            fill_quarter(gbase + ((t + 2) % NSLOTS) * GSLOT,
                         (t + 2) * 128 + wh * 32, ltid);
            CP_COMMIT();
        }

        // ---- S (bf16 3-pass, SPLIT chains) + softmax + bf16 P hi/lo pack
        uint32_t ph[2][4], pl[2][4];
        #pragma unroll
        for (int np = 0; np < 2; np++) {
            float sh0[4] = {0.f, 0.f, 0.f, 0.f};   // Qhi*Khi chain (len 4)
            float sh1[4] = {0.f, 0.f, 0.f, 0.f};
            float sr0[4] = {0.f, 0.f, 0.f, 0.f};   // correction chain (len 8)
            float sr1[4] = {0.f, 0.f, 0.f, 0.f};
            #pragma unroll
            for (int ks = 0; ks < 4; ks++) {
                uint32_t sw = SW128((np * 16 + krow_l) * 128 +
                                    (ks * 16 + kcol_l) * 2);
                uint32_t b0, b1, b2, b3;
                LDSM4(b0, b1, b2, b3, tbase + GOFF_KHI + sw);
                mma16816(sh0, qh[4*ks], qh[4*ks+1], qh[4*ks+2], qh[4*ks+3], b0, b1);
                mma16816(sh1, qh[4*ks], qh[4*ks+1], qh[4*ks+2], qh[4*ks+3], b2, b3);
                mma16816(sr0, ql[4*ks], ql[4*ks+1], ql[4*ks+2], ql[4*ks+3], b0, b1);
                mma16816(sr1, ql[4*ks], ql[4*ks+1], ql[4*ks+2], ql[4*ks+3], b2, b3);
                uint32_t c0, c1, c2, c3;
                LDSM4(c0, c1, c2, c3, tbase + GOFF_KLO + sw);
                mma16816(sr0, qh[4*ks], qh[4*ks+1], qh[4*ks+2], qh[4*ks+3], c0, c1);
                mma16816(sr1, qh[4*ks], qh[4*ks+1], qh[4*ks+2], qh[4*ks+3], c2, c3);
            }
            float s0[4], s1[4];
            #pragma unroll
            for (int j = 0; j < 4; j++) { s0[j] = sh0[j] + sr0[j];
                                          s1[j] = sh1[j] + sr1[j]; }
            int bit = (np << 4) + 2 * tg;
            float p00 = ((mw0 >> bit) & 1u)       ? ex2f(fmaf(s0[0], sc, -mq0)) : 0.f;
            float p01 = ((mw0 >> (bit + 1)) & 1u) ? ex2f(fmaf(s0[1], sc, -mq0)) : 0.f;
            float p02 = ((mw1 >> bit) & 1u)       ? ex2f(fmaf(s0[2], sc, -mq1)) : 0.f;
            float p03 = ((mw1 >> (bit + 1)) & 1u) ? ex2f(fmaf(s0[3], sc, -mq1)) : 0.f;
            float p10 = ((mw0 >> (bit + 8)) & 1u) ? ex2f(fmaf(s1[0], sc, -mq0)) : 0.f;
            float p11 = ((mw0 >> (bit + 9)) & 1u) ? ex2f(fmaf(s1[1], sc, -mq0)) : 0.f;
            float p12 = ((mw1 >> (bit + 8)) & 1u) ? ex2f(fmaf(s1[2], sc, -mq1)) : 0.f;
            float p13 = ((mw1 >> (bit + 9)) & 1u) ? ex2f(fmaf(s1[3], sc, -mq1)) : 0.f;
            l0 += p00 + p01 + p10 + p11;
            l1 += p02 + p03 + p12 + p13;
            packbf(p00, p01, ph[np][0], pl[np][0]);
            packbf(p02, p03, ph[np][1], pl[np][1]);
            packbf(p10, p11, ph[np][2], pl[np][2]);
            packbf(p12, p13, ph[np][3], pl[np][3]);
        }

        // ---- O += P V (bf16 3-pass) over this key quarter
        #pragma unroll
        for (int ks = 0; ks < 2; ks++) {
            #pragma unroll
            for (int np = 0; np < 4; np++) {
                uint32_t sw = SW128((ks * 16 + vrow_l) * 128 +
                                    (np * 16 + vcol_l) * 2);
                uint32_t v0, v1, v2, v3;
                LDSM4T(v0, v1, v2, v3, tbase + GOFF_VHI + sw);
                mma16816(o[2*np],   ph[ks][0], ph[ks][1], ph[ks][2], ph[ks][3], v0, v1);
                mma16816(o[2*np+1], ph[ks][0], ph[ks][1], ph[ks][2], ph[ks][3], v2, v3);
                mma16816(o[2*np],   pl[ks][0], pl[ks][1], pl[ks][2], pl[ks][3], v0, v1);
                mma16816(o[2*np+1], pl[ks][0], pl[ks][1], pl[ks][2], pl[ks][3], v2, v3);
                uint32_t u0, u1, u2, u3;
                LDSM4T(u0, u1, u2, u3, tbase + GOFF_VLO + sw);
                mma16816(o[2*np],   ph[ks][0], ph[ks][1], ph[ks][2], ph[ks][3], u0, u1);
                mma16816(o[2*np+1], ph[ks][0], ph[ks][1], ph[ks][2], ph[ks][3], u2, u3);
            }
        }
    }

    // ---- combine 4 key quarters: wh>0 dump partials, wh==0 finalizes.
    __syncthreads();
    float* cmb = (float*)smem;   // 3*128*34 floats = 52KB (slots free now)
    if (wh > 0) {
        float* dst = cmb + ((wh - 1) * 128 + wq * 32 + lane) * 34;
        #pragma unroll
        for (int i = 0; i < 8; i++)
            #pragma unroll
            for (int j = 0; j < 4; j++) dst[i * 4 + j] = o[i][j];
        dst[32] = l0;
        dst[33] = l1;
    }
    __syncthreads();
    if (wh == 0) {
        #pragma unroll
        for (int q = 0; q < 3; q++) {
            const float* src = cmb + (q * 128 + wq * 32 + lane) * 34;
            #pragma unroll
            for (int i = 0; i < 8; i++)
                #pragma unroll
                for (int j = 0; j < 4; j++) o[i][j] += src[i * 4 + j];
            l0 += src[32];
            l1 += src[33];
        }
        l0 += __shfl_xor_sync(0xffffffffu, l0, 1);
        l0 += __shfl_xor_sync(0xffffffffu, l0, 2);
        l1 += __shfl_xor_sync(0xffffffffu, l1, 1);
        l1 += __shfl_xor_sync(0xffffffffu, l1, 2);
        float inv0 = 1.f / l0, inv1 = 1.f / l1;

        int gr0 = qbase + q0 + g, gr1 = gr0 + 8;
        #pragma unroll
        for (int nt = 0; nt < 8; nt++) {
            float x0 = o[nt][0] * inv0; x0 = (x0 > 0.f) ? x0 : expm1f(x0);
            float x1 = o[nt][1] * inv0; x1 = (x1 > 0.f) ? x1 : expm1f(x1);
            float x2 = o[nt][2] * inv1; x2 = (x2 > 0.f) ? x2 : expm1f(x2);
            float x3 = o[nt][3] * inv1; x3 = (x3 > 0.f) ? x3 : expm1f(x3);
            *(float2*)(out + (long)gr0 * DD + nt * 8 + 2 * tg) = make_float2(x0, x1);
            *(float2*)(out + (long)gr1 * DD + nt * 8 + 2 * tg) = make_float2(x2, x3);
        }
    }
}

namespace {
struct AttrInit {
    AttrInit() {
        cudaFuncSetAttribute(attn_kernel,
                             cudaFuncAttributeMaxDynamicSharedMemorySize,
                             SMEM_ATTN);
    }
} attr_init_;
}

extern "C" void kernel_launch(void* const* d_in, const int* in_sizes, int n_in,
                              void* d_out, int out_size) {
    const float* inp = nullptr;
    const int*   adj = nullptr;
    const float* kW  = nullptr;
    const float* vW  = nullptr;
    for (int i = 0; i < n_in; i++) {
        long sz = in_sizes[i];
        if (sz == (long)NN * DIN)      inp = (const float*)d_in[i];
        else if (sz == (long)NN * NN)  adj = (const int*)d_in[i];
        else if (sz == (long)DIN * DD) { if (!kW) kW = (const float*)d_in[i];
                                         else     vW = (const float*)d_in[i]; }
    }
    float* out = (float*)d_out;

    cudaFuncSetAttribute(attn_kernel,
                         cudaFuncAttributeMaxDynamicSharedMemorySize, SMEM_ATTN);

    prep_kernel<<<PROJ_CTAS + MASK_CTAS, 256>>>(inp, kW, vW, adj);
    attn_kernel<<<NN / 64, 512, SMEM_ATTN>>>(out);
}

// round 16
// speedup vs baseline: 1.0131x; 1.0131x over previous
#include <cuda_runtime.h>
#include <cuda_bf16.h>
#include <math.h>
#include <stdint.h>

#define NN   8192
#define DIN  512
#define DD   64

// ===========================================================================
// Device globals (no allocation allowed).
// ===========================================================================
__device__ __nv_bfloat16  g_khhi[NN * DD];
__device__ __nv_bfloat16  g_khlo[NN * DD];
__device__ __nv_bfloat16  g_vhhi[NN * DD];
__device__ __nv_bfloat16  g_vhlo[NN * DD];
__device__ float          g_norm[NN];
__device__ unsigned       g_maxnorm_bits;   // reset in prep CTA0; atomicMax after

// ===========================================================================
// Helpers
// ===========================================================================
__device__ __forceinline__ uint32_t smem_u32(const void* p) {
    uint32_t a;
    asm("{ .reg .u64 t; cvta.to.shared.u64 t, %1; cvt.u32.u64 %0, t; }"
        : "=r"(a) : "l"(p));
    return a;
}
#define SW128(x) ((uint32_t)(x) ^ ((((uint32_t)(x)) >> 3) & 0x70))

__device__ __forceinline__ void mma16816(float* d,
    uint32_t a0, uint32_t a1, uint32_t a2, uint32_t a3,
    uint32_t b0, uint32_t b1) {
    asm volatile(
        "mma.sync.aligned.m16n8k16.row.col.f32.bf16.bf16.f32 "
        "{%0,%1,%2,%3},{%4,%5,%6,%7},{%8,%9},{%0,%1,%2,%3};"
        : "+f"(d[0]), "+f"(d[1]), "+f"(d[2]), "+f"(d[3])
        : "r"(a0), "r"(a1), "r"(a2), "r"(a3), "r"(b0), "r"(b1));
}
#define LDSM4(r0, r1, r2, r3, a)                                        \
    asm volatile("ldmatrix.sync.aligned.m8n8.x4.shared.b16 "            \
                 "{%0,%1,%2,%3}, [%4];"                                 \
                 : "=r"(r0), "=r"(r1), "=r"(r2), "=r"(r3) : "r"(a))
#define LDSM4T(r0, r1, r2, r3, a)                                       \
    asm volatile("ldmatrix.sync.aligned.m8n8.x4.trans.shared.b16 "      \
                 "{%0,%1,%2,%3}, [%4];"                                 \
                 : "=r"(r0), "=r"(r1), "=r"(r2), "=r"(r3) : "r"(a))
#define CP16(dst, src)                                                  \
    asm volatile("cp.async.cg.shared.global [%0], [%1], 16;"            \
                 :: "r"(dst), "l"(src))
#define CP_COMMIT() asm volatile("cp.async.commit_group;" ::: "memory")
#define BAR_GRP(id) asm volatile("bar.sync %0, 128;" :: "r"(id) : "memory")
#define LDS2(x, y, a)                                                   \
    asm volatile("ld.shared.v2.u32 {%0,%1}, [%2];"                      \
                 : "=r"(x), "=r"(y) : "r"(a))

__device__ __forceinline__ float ex2f(float x) {
    float r;
    asm("ex2.approx.ftz.f32 %0, %1;" : "=f"(r) : "f"(x));
    return r;
}

// Pack p0 (lo) / p1 (hi) into bf16x2 hi-part + exact fp32 residual bf16x2.
__device__ __forceinline__ void packbf(float p0, float p1,
                                       uint32_t& hv, uint32_t& rv) {
    asm("cvt.rn.bf16x2.f32 %0, %1, %2;" : "=r"(hv) : "f"(p1), "f"(p0));
    float h0 = __uint_as_float(hv << 16);
    float h1 = __uint_as_float(hv & 0xFFFF0000u);
    asm("cvt.rn.bf16x2.f32 %0, %1, %2;" : "=r"(rv) : "f"(p1 - h1), "f"(p0 - h0));
}

// ===========================================================================
// Stage 1: projection only (mask pass eliminated — adj is read by attn).
// 256 CTAs x 32 rows, 256 threads (2 CTAs co-resident on most SMs).
// ===========================================================================
__global__ void __launch_bounds__(256) prep_kernel(const float* __restrict__ inp,
                                                   const float* __restrict__ kW,
                                                   const float* __restrict__ vW) {
    __shared__ float sIn[32][36];
    __shared__ float sKW[32][65];
    __shared__ float sVW[32][65];
    const int tid = threadIdx.x;
    const int tx = tid & 15, ty = tid >> 4;
    if (blockIdx.x == 0 && tid == 0) g_maxnorm_bits = 0u;
    const int rbase = blockIdx.x * 32;
    float ak[2][4] = {}, av[2][4] = {};

    for (int kc = 0; kc < DIN; kc += 32) {
        __syncthreads();
        for (int e = tid; e < 32 * 32; e += 256) {
            int r = e >> 5, c = e & 31;
            sIn[r][c] = inp[(rbase + r) * DIN + kc + c];
        }
        for (int e = tid; e < 32 * 64; e += 256) {
            int r = e >> 6, c = e & 63;
            sKW[r][c] = kW[(kc + r) * DD + c];
            sVW[r][c] = vW[(kc + r) * DD + c];
        }
        __syncthreads();
        #pragma unroll 8
        for (int kk = 0; kk < 32; kk++) {
            float a[2], bk[4], bv[4];
            #pragma unroll
            for (int i = 0; i < 2; i++) a[i] = sIn[ty + 16 * i][kk];
            #pragma unroll
            for (int j = 0; j < 4; j++) { bk[j] = sKW[kk][tx + 16 * j];
                                          bv[j] = sVW[kk][tx + 16 * j]; }
            #pragma unroll
            for (int i = 0; i < 2; i++)
                #pragma unroll
                for (int j = 0; j < 4; j++) {
                    ak[i][j] = fmaf(a[i], bk[j], ak[i][j]);
                    av[i][j] = fmaf(a[i], bv[j], av[i][j]);
                }
        }
    }

    #pragma unroll
    for (int i = 0; i < 2; i++) {
        float part = 0.f;
        #pragma unroll
        for (int j = 0; j < 4; j++) {
            int idx = (rbase + ty + 16 * i) * DD + tx + 16 * j;
            float kv = ak[i][j], vv = av[i][j];
            part = fmaf(kv, kv, part);
            __nv_bfloat16 kh = __float2bfloat16(kv);
            g_khhi[idx] = kh;
            g_khlo[idx] = __float2bfloat16(kv - __bfloat162float(kh));
            __nv_bfloat16 vh = __float2bfloat16(vv);
            g_vhhi[idx] = vh;
            g_vhlo[idx] = __float2bfloat16(vv - __bfloat162float(vh));
        }
        #pragma unroll
        for (int off = 1; off < 16; off <<= 1)
            part += __shfl_xor_sync(0xffffffffu, part, off);
        if (tx == 0) {
            float n = sqrtf(part);
            g_norm[rbase + ty + 16 * i] = n;
            atomicMax(&g_maxnorm_bits, __float_as_uint(n));
        }
    }
}

// ===========================================================================
// Stage 2: HMMA flash attention, fixed per-row max.
// grid = 128 (64 q rows / CTA), 512 threads (16 warps).
// warp w: q-band (w&3)*16, key quarter wh=(w>>2)*32.
// Per-group 2-slot pipelines (named barriers). Each slot carries the group's
// K/V quarter (bf16 hi/lo, SW128) AND the raw adj tile (64 rows x 32 keys,
// int32, row stride 128B) — adj streams from DRAM under the tensor loop.
// ===========================================================================
#define GOFF_KHI 0
#define GOFF_KLO 4096
#define GOFF_VHI 8192
#define GOFF_VLO 12288
#define GOFF_ADJ 16384
#define GSLOT 24576                  // 16KB K/V + 8KB adj
#define NSLOTS 2
#define GRP_BYTES (NSLOTS * GSLOT)   // 48KB per group
#define SMEM_ATTN (4 * GRP_BYTES)    // 192KB
#define TILES (NN / 128)

// Fill this group's quarter (keys [kq, kq+32)) of a tile + its adj block.
__device__ __forceinline__ void fill_quarter(uint32_t gslot,
                                             const int* __restrict__ adj,
                                             int qbase, int kq, int ltid) {
    #pragma unroll
    for (int i = 0; i < 2; i++) {
        int e = i * 128 + ltid;      // 256 16B units per array
        int r = e >> 3, b = e & 7;
        uint32_t sw = SW128(r * 128 + b * 16);
        long src = (long)(kq + r) * DD + b * 8;
        CP16(gslot + GOFF_KHI + sw, g_khhi + src);
        CP16(gslot + GOFF_KLO + sw, g_khlo + src);
        CP16(gslot + GOFF_VHI + sw, g_vhhi + src);
        CP16(gslot + GOFF_VLO + sw, g_vhlo + src);
    }
    #pragma unroll
    for (int i = 0; i < 4; i++) {
        int e = i * 128 + ltid;      // 512 16B units (64 rows x 128B)
        int r = e >> 3, u = e & 7;
        CP16(gslot + GOFF_ADJ + r * 128 + u * 16,
             adj + (long)(qbase + r) * NN + kq + u * 4);
    }
}

__global__ void __launch_bounds__(512, 1)
attn_kernel(const int* __restrict__ adj, float* __restrict__ out) {
    extern __shared__ char smem[];
    const uint32_t sb = smem_u32(smem);
    const int tid  = threadIdx.x;
    const int w    = tid >> 5;
    const int lane = tid & 31;
    const int wq   = w & 3;              // q band
    const int wh   = w >> 2;             // key quarter (0..3) == group
    const int ltid = tid & 127;          // thread id within group
    const int g    = lane >> 2;
    const int tg   = lane & 3;
    const int q0   = wq * 16;
    const int qbase = blockIdx.x * 64;
    const uint32_t gbase = sb + wh * GRP_BYTES;

    // ---- Stage Q at sb (hi) / sb+8192 (lo), extract A fragments.
    {
        int e = tid;                     // 512 16B units
        int r = e >> 3, b = e & 7;
        uint32_t sw = SW128(r * 128 + b * 16);
        *(uint4*)(smem + sw) =
            *(const uint4*)(g_khhi + (qbase + r) * DD + b * 8);
        *(uint4*)(smem + 8192 + sw) =
            *(const uint4*)(g_khlo + (qbase + r) * DD + b * 8);
    }
    __syncthreads();

    uint32_t qh[16], ql[16];
    {
        int arow = q0 + ((lane >> 3) & 1) * 8 + (lane & 7);
        int acol0 = (lane >> 4) * 8;
        #pragma unroll
        for (int ks = 0; ks < 4; ks++) {
            uint32_t sw = SW128(arow * 128 + (ks * 16 + acol0) * 2);
            LDSM4(qh[4*ks], qh[4*ks+1], qh[4*ks+2], qh[4*ks+3], sb + sw);
            LDSM4(ql[4*ks], ql[4*ks+1], ql[4*ks+2], ql[4*ks+3], sb + 8192 + sw);
        }
    }
    __syncthreads();   // Q region free (overlaps group 0 slot 0)

    // Prologue fill for tile 0 (this group's quarter).
    fill_quarter(gbase, adj, qbase, wh * 32, ltid);
    CP_COMMIT();

    // exp in log2 domain: p = 2^(s*c - m').
    const float C_LOG2E = 1.4426950408889634f;
    const float sc = 0.125f * C_LOG2E;
    const float maxn = __uint_as_float(g_maxnorm_bits) * 0.125f * 1.0001f * C_LOG2E;
    const float mq0 = g_norm[qbase + q0 + g] * maxn;
    const float mq1 = g_norm[qbase + q0 + g + 8] * maxn;

    float o[8][4];
    #pragma unroll
    for (int i = 0; i < 8; i++)
        #pragma unroll
        for (int j = 0; j < 4; j++) o[i][j] = 0.f;
    float l0 = 0.f, l1 = 0.f;

    const int krow_l = (lane >> 4) * 8 + (lane & 7);
    const int kcol_l = ((lane >> 3) & 1) * 8;
    const int vrow_l = ((lane >> 3) & 1) * 8 + (lane & 7);
    const int vcol_l = (lane >> 4) * 8;

    for (int t = 0; t < TILES; t++) {
        const uint32_t tbase = gbase + (t & 1) * GSLOT;

        // wait for this group's tile-t fill; group barrier also guarantees
        // everyone finished reading the other slot (tile t-1).
        asm volatile("cp.async.wait_group 0;" ::: "memory");
        BAR_GRP(wh + 1);

        if (t + 1 < TILES) {
            fill_quarter(gbase + ((t + 1) & 1) * GSLOT, adj, qbase,
                         (t + 1) * 128 + wh * 32, ltid);
            CP_COMMIT();
        }

        // ---- S (bf16 3-pass) + softmax (adj via broadcast LDS) + P pack
        uint32_t ph[2][4], pl[2][4];
        #pragma unroll
        for (int np = 0; np < 2; np++) {
            float s0[4] = {0.f, 0.f, 0.f, 0.f};
            float s1[4] = {0.f, 0.f, 0.f, 0.f};
            #pragma unroll
            for (int ks = 0; ks < 4; ks++) {
                uint32_t sw = SW128((np * 16 + krow_l) * 128 +
                                    (ks * 16 + kcol_l) * 2);
                uint32_t b0, b1, b2, b3;
                LDSM4(b0, b1, b2, b3, tbase + GOFF_KHI + sw);
                mma16816(s0, qh[4*ks], qh[4*ks+1], qh[4*ks+2], qh[4*ks+3], b0, b1);
                mma16816(s1, qh[4*ks], qh[4*ks+1], qh[4*ks+2], qh[4*ks+3], b2, b3);
                mma16816(s0, ql[4*ks], ql[4*ks+1], ql[4*ks+2], ql[4*ks+3], b0, b1);
                mma16816(s1, ql[4*ks], ql[4*ks+1], ql[4*ks+2], ql[4*ks+3], b2, b3);
                uint32_t c0, c1, c2, c3;
                LDSM4(c0, c1, c2, c3, tbase + GOFF_KLO + sw);
                mma16816(s0, qh[4*ks], qh[4*ks+1], qh[4*ks+2], qh[4*ks+3], c0, c1);
                mma16816(s1, qh[4*ks], qh[4*ks+1], qh[4*ks+2], qh[4*ks+3], c2, c3);
            }
            // adj values for rows (q0+g, q0+g+8), keys np*16 + {2tg,2tg+1,+8,+9}
            uint32_t abase = tbase + GOFF_ADJ + (q0 + g) * 128 +
                             (np * 16 + 2 * tg) * 4;
            int a00x, a00y, a10x, a10y, a01x, a01y, a11x, a11y;
            LDS2(a00x, a00y, abase);               // row g,   keys 2tg,2tg+1
            LDS2(a10x, a10y, abase + 32);          // row g,   keys +8,+9
            LDS2(a01x, a01y, abase + 1024);        // row g+8, keys 2tg,2tg+1
            LDS2(a11x, a11y, abase + 1024 + 32);   // row g+8, keys +8,+9
            float p00 = (a00x > 0) ? ex2f(fmaf(s0[0], sc, -mq0)) : 0.f;
            float p01 = (a00y > 0) ? ex2f(fmaf(s0[1], sc, -mq0)) : 0.f;
            float p02 = (a01x > 0) ? ex2f(fmaf(s0[2], sc, -mq1)) : 0.f;
            float p03 = (a01y > 0) ? ex2f(fmaf(s0[3], sc, -mq1)) : 0.f;
            float p10 = (a10x > 0) ? ex2f(fmaf(s1[0], sc, -mq0)) : 0.f;
            float p11 = (a10y > 0) ? ex2f(fmaf(s1[1], sc, -mq0)) : 0.f;
            float p12 = (a11x > 0) ? ex2f(fmaf(s1[2], sc, -mq1)) : 0.f;
            float p13 = (a11y > 0) ? ex2f(fmaf(s1[3], sc, -mq1)) : 0.f;
            l0 += p00 + p01 + p10 + p11;
            l1 += p02 + p03 + p12 + p13;
            packbf(p00, p01, ph[np][0], pl[np][0]);
            packbf(p02, p03, ph[np][1], pl[np][1]);
            packbf(p10, p11, ph[np][2], pl[np][2]);
            packbf(p12, p13, ph[np][3], pl[np][3]);
        }

        // ---- O += P V (bf16 3-pass) over this key quarter
        #pragma unroll
        for (int ks = 0; ks < 2; ks++) {
            #pragma unroll
            for (int np = 0; np < 4; np++) {
                uint32_t sw = SW128((ks * 16 + vrow_l) * 128 +
                                    (np * 16 + vcol_l) * 2);
                uint32_t v0, v1, v2, v3;
                LDSM4T(v0, v1, v2, v3, tbase + GOFF_VHI + sw);
                mma16816(o[2*np],   ph[ks][0], ph[ks][1], ph[ks][2], ph[ks][3], v0, v1);
                mma16816(o[2*np+1], ph[ks][0], ph[ks][1], ph[ks][2], ph[ks][3], v2, v3);
                mma16816(o[2*np],   pl[ks][0], pl[ks][1], pl[ks][2], pl[ks][3], v0, v1);
                mma16816(o[2*np+1], pl[ks][0], pl[ks][1], pl[ks][2], pl[ks][3], v2, v3);
                uint32_t u0, u1, u2, u3;
                LDSM4T(u0, u1, u2, u3, tbase + GOFF_VLO + sw);
                mma16816(o[2*np],   ph[ks][0], ph[ks][1], ph[ks][2], ph[ks][3], u0, u1);
                mma16816(o[2*np+1], ph[ks][0], ph[ks][1], ph[ks][2], ph[ks][3], u2, u3);
            }
        }
    }

    // ---- combine 4 key quarters: wh>0 dump partials, wh==0 finalizes.
    __syncthreads();
    float* cmb = (float*)smem;   // 3*128*34 floats = 52KB (slots free now)
    if (wh > 0) {
        float* dst = cmb + ((wh - 1) * 128 + wq * 32 + lane) * 34;
        #pragma unroll
        for (int i = 0; i < 8; i++)
            #pragma unroll
            for (int j = 0; j < 4; j++) dst[i * 4 + j] = o[i][j];
        dst[32] = l0;
        dst[33] = l1;
    }
    __syncthreads();
    if (wh == 0) {
        #pragma unroll
        for (int q = 0; q < 3; q++) {
            const float* src = cmb + (q * 128 + wq * 32 + lane) * 34;
            #pragma unroll
            for (int i = 0; i < 8; i++)
                #pragma unroll
                for (int j = 0; j < 4; j++) o[i][j] += src[i * 4 + j];
            l0 += src[32];
            l1 += src[33];
        }
        l0 += __shfl_xor_sync(0xffffffffu, l0, 1);
        l0 += __shfl_xor_sync(0xffffffffu, l0, 2);
        l1 += __shfl_xor_sync(0xffffffffu, l1, 1);
        l1 += __shfl_xor_sync(0xffffffffu, l1, 2);
        float inv0 = 1.f / l0, inv1 = 1.f / l1;

        int gr0 = qbase + q0 + g, gr1 = gr0 + 8;
        #pragma unroll
        for (int nt = 0; nt < 8; nt++) {
            float x0 = o[nt][0] * inv0; x0 = (x0 > 0.f) ? x0 : expm1f(x0);
            float x1 = o[nt][1] * inv0; x1 = (x1 > 0.f) ? x1 : expm1f(x1);
            float x2 = o[nt][2] * inv1; x2 = (x2 > 0.f) ? x2 : expm1f(x2);
            float x3 = o[nt][3] * inv1; x3 = (x3 > 0.f) ? x3 : expm1f(x3);
            *(float2*)(out + (long)gr0 * DD + nt * 8 + 2 * tg) = make_float2(x0, x1);
            *(float2*)(out + (long)gr1 * DD + nt * 8 + 2 * tg) = make_float2(x2, x3);
        }
    }
}

namespace {
struct AttrInit {
    AttrInit() {
        cudaFuncSetAttribute(attn_kernel,
                             cudaFuncAttributeMaxDynamicSharedMemorySize,
                             SMEM_ATTN);
    }
} attr_init_;
}

extern "C" void kernel_launch(void* const* d_in, const int* in_sizes, int n_in,
                              void* d_out, int out_size) {
    const float* inp = nullptr;
    const int*   adj = nullptr;
    const float* kW  = nullptr;
    const float* vW  = nullptr;
    for (int i = 0; i < n_in; i++) {
        long sz = in_sizes[i];
        if (sz == (long)NN * DIN)      inp = (const float*)d_in[i];
        else if (sz == (long)NN * NN)  adj = (const int*)d_in[i];
        else if (sz == (long)DIN * DD) { if (!kW) kW = (const float*)d_in[i];
                                         else     vW = (const float*)d_in[i]; }
    }
    float* out = (float*)d_out;

    cudaFuncSetAttribute(attn_kernel,
                         cudaFuncAttributeMaxDynamicSharedMemorySize, SMEM_ATTN);

    prep_kernel<<<NN / 32, 256>>>(inp, kW, vW);
    attn_kernel<<<NN / 64, 512, SMEM_ATTN>>>(adj, out);
}

// round 17
// speedup vs baseline: 1.1327x; 1.1180x over previous
#include <cuda_runtime.h>
#include <cuda_bf16.h>
#include <math.h>
#include <stdint.h>

#define NN   8192
#define DIN  512
#define DD   64

// ===========================================================================
// Device globals (no allocation allowed).
// ===========================================================================
__device__ __nv_bfloat16  g_khhi[NN * DD];
__device__ __nv_bfloat16  g_khlo[NN * DD];
__device__ __nv_bfloat16  g_vhhi[NN * DD];
__device__ __nv_bfloat16  g_vhlo[NN * DD];
__device__ float          g_norm[NN];
__device__ unsigned       g_maxnorm_bits;   // reset in prep CTA0; atomicMax after
__device__ unsigned       g_mask[NN * (NN / 32)];   // 8MB bitmask

// ===========================================================================
// Helpers
// ===========================================================================
__device__ __forceinline__ uint32_t smem_u32(const void* p) {
    uint32_t a;
    asm("{ .reg .u64 t; cvta.to.shared.u64 t, %1; cvt.u32.u64 %0, t; }"
        : "=r"(a) : "l"(p));
    return a;
}
#define SW128(x) ((uint32_t)(x) ^ ((((uint32_t)(x)) >> 3) & 0x70))

__device__ __forceinline__ void mma16816(float* d,
    uint32_t a0, uint32_t a1, uint32_t a2, uint32_t a3,
    uint32_t b0, uint32_t b1) {
    asm volatile(
        "mma.sync.aligned.m16n8k16.row.col.f32.bf16.bf16.f32 "
        "{%0,%1,%2,%3},{%4,%5,%6,%7},{%8,%9},{%0,%1,%2,%3};"
        : "+f"(d[0]), "+f"(d[1]), "+f"(d[2]), "+f"(d[3])
        : "r"(a0), "r"(a1), "r"(a2), "r"(a3), "r"(b0), "r"(b1));
}
#define LDSM4(r0, r1, r2, r3, a)                                        \
    asm volatile("ldmatrix.sync.aligned.m8n8.x4.shared.b16 "            \
                 "{%0,%1,%2,%3}, [%4];"                                 \
                 : "=r"(r0), "=r"(r1), "=r"(r2), "=r"(r3) : "r"(a))
#define LDSM4T(r0, r1, r2, r3, a)                                       \
    asm volatile("ldmatrix.sync.aligned.m8n8.x4.trans.shared.b16 "      \
                 "{%0,%1,%2,%3}, [%4];"                                 \
                 : "=r"(r0), "=r"(r1), "=r"(r2), "=r"(r3) : "r"(a))
#define CP16(dst, src)                                                  \
    asm volatile("cp.async.cg.shared.global [%0], [%1], 16;"            \
                 :: "r"(dst), "l"(src))
#define CP_COMMIT() asm volatile("cp.async.commit_group;" ::: "memory")
#define BAR_GRP(id) asm volatile("bar.sync %0, 128;" :: "r"(id) : "memory")

__device__ __forceinline__ float ex2f(float x) {
    float r;
    asm("ex2.approx.ftz.f32 %0, %1;" : "=f"(r) : "f"(x));
    return r;
}

// Pack p0 (lo) / p1 (hi) into bf16x2 hi-part + exact fp32 residual bf16x2.
__device__ __forceinline__ void packbf(float p0, float p1,
                                       uint32_t& hv, uint32_t& rv) {
    asm("cvt.rn.bf16x2.f32 %0, %1, %2;" : "=r"(hv) : "f"(p1), "f"(p0));
    float h0 = __uint_as_float(hv << 16);
    float h1 = __uint_as_float(hv & 0xFFFF0000u);
    asm("cvt.rn.bf16x2.f32 %0, %1, %2;" : "=r"(rv) : "f"(p1 - h1), "f"(p0 - h0));
}

// ===========================================================================
// Stage 1: ONE heterogeneous launch.
//   blockIdx < 128   : projection CTAs (vectorized LDS.128 weights) + norms
//   blockIdx >= 128  : 2048 mask-packing CTAs (DRAM-bound streaming)
// Proj thread (tx,ty): rows ty+16i (i<4), cols 4tx..4tx+3 (contiguous!).
// Per kk: 4 broadcast a-loads + 2 LDS.128 weight loads feed 32 FMAs.
// ===========================================================================
#define PROJ_CTAS 128
#define MASK_CTAS 2048

__global__ void __launch_bounds__(256) prep_kernel(const float* __restrict__ inp,
                                                   const float* __restrict__ kW,
                                                   const float* __restrict__ vW,
                                                   const int* __restrict__ adj) {
    const int tid = threadIdx.x;

    if (blockIdx.x >= PROJ_CTAS) {
        // ---- mask role: warp packs 128 consecutive 32-key words, MLP=16.
        const int warp = ((blockIdx.x - PROJ_CTAS) * 256 + tid) >> 5;
        const int lane = tid & 31;
        const long base = (long)warp * 128;
        for (int i0 = 0; i0 < 128; i0 += 16) {
            int v[16];
            #pragma unroll
            for (int u = 0; u < 16; u++)
                v[u] = adj[(base + i0 + u) * 32 + lane];
            #pragma unroll
            for (int u = 0; u < 16; u++) {
                unsigned b = __ballot_sync(0xffffffffu, v[u] > 0);
                if (lane == 0) g_mask[base + i0 + u] = b;
            }
        }
        return;
    }

    // ---- projection role (vectorized operands).
    __shared__ float sIn[64][36];       // float4-fillable; a-loads 2-way max
    __shared__ float sKW[32][64];       // 256B rows, LDS.128 at col 4*tx
    __shared__ float sVW[32][64];
    const int tx = tid & 15, ty = tid >> 4;
    if (blockIdx.x == 0 && tid == 0) g_maxnorm_bits = 0u;
    const int rbase = blockIdx.x * 64;
    float ak[4][4] = {}, av[4][4] = {};

    for (int kc = 0; kc < DIN; kc += 32) {
        __syncthreads();
        // sIn: 64 rows x 32 floats = 512 float4
        #pragma unroll
        for (int e = tid; e < 512; e += 256) {
            int r = e >> 3, q = e & 7;
            *(float4*)&sIn[r][q * 4] =
                *(const float4*)&inp[(rbase + r) * DIN + kc + q * 4];
        }
        // sKW/sVW: 32 rows x 64 floats = 512 float4 each
        #pragma unroll
        for (int e = tid; e < 512; e += 256) {
            int r = e >> 4, q = e & 15;
            *(float4*)&sKW[r][q * 4] =
                *(const float4*)&kW[(kc + r) * DD + q * 4];
            *(float4*)&sVW[r][q * 4] =
                *(const float4*)&vW[(kc + r) * DD + q * 4];
        }
        __syncthreads();
        #pragma unroll 8
        for (int kk = 0; kk < 32; kk++) {
            float a[4];
            #pragma unroll
            for (int i = 0; i < 4; i++) a[i] = sIn[ty + 16 * i][kk];
            float4 bk = *(const float4*)&sKW[kk][tx * 4];
            float4 bv = *(const float4*)&sVW[kk][tx * 4];
            #pragma unroll
            for (int i = 0; i < 4; i++) {
                ak[i][0] = fmaf(a[i], bk.x, ak[i][0]);
                ak[i][1] = fmaf(a[i], bk.y, ak[i][1]);
                ak[i][2] = fmaf(a[i], bk.z, ak[i][2]);
                ak[i][3] = fmaf(a[i], bk.w, ak[i][3]);
                av[i][0] = fmaf(a[i], bv.x, av[i][0]);
                av[i][1] = fmaf(a[i], bv.y, av[i][1]);
                av[i][2] = fmaf(a[i], bv.z, av[i][2]);
                av[i][3] = fmaf(a[i], bv.w, av[i][3]);
            }
        }
    }

    // Epilogue: bf16 hi/lo splits (vector stores) + fused row norms.
    #pragma unroll
    for (int i = 0; i < 4; i++) {
        int row = rbase + ty + 16 * i;
        long off = (long)row * DD + 4 * tx;
        float part = 0.f;
        uint32_t kh01, kh23, kl01, kl23, vh01, vh23, vl01, vl23;
        packbf(ak[i][0], ak[i][1], kh01, kl01);
        packbf(ak[i][2], ak[i][3], kh23, kl23);
        packbf(av[i][0], av[i][1], vh01, vl01);
        packbf(av[i][2], av[i][3], vh23, vl23);
        #pragma unroll
        for (int j = 0; j < 4; j++) part = fmaf(ak[i][j], ak[i][j], part);
        *(uint2*)&g_khhi[off] = make_uint2(kh01, kh23);
        *(uint2*)&g_khlo[off] = make_uint2(kl01, kl23);
        *(uint2*)&g_vhhi[off] = make_uint2(vh01, vh23);
        *(uint2*)&g_vhlo[off] = make_uint2(vl01, vl23);
        #pragma unroll
        for (int offx = 1; offx < 16; offx <<= 1)
            part += __shfl_xor_sync(0xffffffffu, part, offx);
        if (tx == 0) {
            float n = sqrtf(part);
            g_norm[row] = n;
            atomicMax(&g_maxnorm_bits, __float_as_uint(n));
        }
    }
}

// ===========================================================================
// Stage 2: HMMA flash attention, fixed per-row max (exact round-14 engine).
// grid = 128 (64 q rows / CTA), 512 threads (16 warps).
// warp w: q-band (w&3)*16, key quarter wh=(w>>2)*32.
// Per-group 3-slot pipelines with named barriers.
// ===========================================================================
#define GSLOT 16384                  // per-group slot: Kq hi/lo + Vq hi/lo
#define GOFF_KHI 0
#define GOFF_KLO 4096
#define GOFF_VHI 8192
#define GOFF_VLO 12288
#define NSLOTS 3
#define GRP_BYTES (NSLOTS * GSLOT)   // 48KB per group
#define SMEM_ATTN (4 * GRP_BYTES)    // 192KB
#define TILES (NN / 128)

__device__ __forceinline__ void fill_quarter(uint32_t gslot, int kq, int ltid) {
    #pragma unroll
    for (int i = 0; i < 2; i++) {
        int e = i * 128 + ltid;      // 256 16B units per array
        int r = e >> 3, b = e & 7;
        uint32_t sw = SW128(r * 128 + b * 16);
        long src = (long)(kq + r) * DD + b * 8;
        CP16(gslot + GOFF_KHI + sw, g_khhi + src);
        CP16(gslot + GOFF_KLO + sw, g_khlo + src);
        CP16(gslot + GOFF_VHI + sw, g_vhhi + src);
        CP16(gslot + GOFF_VLO + sw, g_vhlo + src);
    }
}

__global__ void __launch_bounds__(512, 1)
attn_kernel(float* __restrict__ out) {
    extern __shared__ char smem[];
    const uint32_t sb = smem_u32(smem);
    const int tid  = threadIdx.x;
    const int w    = tid >> 5;
    const int lane = tid & 31;
    const int wq   = w & 3;              // q band
    const int wh   = w >> 2;             // key quarter (0..3) == group
    const int ltid = tid & 127;          // thread id within group
    const int g    = lane >> 2;
    const int tg   = lane & 3;
    const int q0   = wq * 16;
    const int qbase = blockIdx.x * 64;
    const uint32_t gbase = sb + wh * GRP_BYTES;

    // ---- Stage Q at sb (hi) / sb+8192 (lo), extract A fragments.
    {
        int e = tid;                     // 512 16B units
        int r = e >> 3, b = e & 7;
        uint32_t sw = SW128(r * 128 + b * 16);
        *(uint4*)(smem + sw) =
            *(const uint4*)(g_khhi + (qbase + r) * DD + b * 8);
        *(uint4*)(smem + 8192 + sw) =
            *(const uint4*)(g_khlo + (qbase + r) * DD + b * 8);
    }
    __syncthreads();

    uint32_t qh[16], ql[16];
    {
        int arow = q0 + ((lane >> 3) & 1) * 8 + (lane & 7);
        int acol0 = (lane >> 4) * 8;
        #pragma unroll
        for (int ks = 0; ks < 4; ks++) {
            uint32_t sw = SW128(arow * 128 + (ks * 16 + acol0) * 2);
            LDSM4(qh[4*ks], qh[4*ks+1], qh[4*ks+2], qh[4*ks+3], sb + sw);
            LDSM4(ql[4*ks], ql[4*ks+1], ql[4*ks+2], ql[4*ks+3], sb + 8192 + sw);
        }
    }
    __syncthreads();   // Q region free (overlaps group 0 slots)

    // Prologue fills for tiles 0 and 1 (this group's quarters).
    fill_quarter(gbase + 0 * GSLOT, 0 * 128 + wh * 32, ltid);
    CP_COMMIT();
    fill_quarter(gbase + 1 * GSLOT, 1 * 128 + wh * 32, ltid);
    CP_COMMIT();

    // exp in log2 domain: p = 2^(s*c - m').
    const float C_LOG2E = 1.4426950408889634f;
    const float sc = 0.125f * C_LOG2E;
    const float maxn = __uint_as_float(g_maxnorm_bits) * 0.125f * 1.0001f * C_LOG2E;
    const float mq0 = g_norm[qbase + q0 + g] * maxn;
    const float mq1 = g_norm[qbase + q0 + g + 8] * maxn;
    const unsigned* mrow0 = g_mask + (long)(qbase + q0 + g) * (NN / 32) + wh;
    const unsigned* mrow1 = g_mask + (long)(qbase + q0 + g + 8) * (NN / 32) + wh;

    float o[8][4];
    #pragma unroll
    for (int i = 0; i < 8; i++)
        #pragma unroll
        for (int j = 0; j < 4; j++) o[i][j] = 0.f;
    float l0 = 0.f, l1 = 0.f;

    const int krow_l = (lane >> 4) * 8 + (lane & 7);
    const int kcol_l = ((lane >> 3) & 1) * 8;
    const int vrow_l = ((lane >> 3) & 1) * 8 + (lane & 7);
    const int vcol_l = (lane >> 4) * 8;

    for (int t = 0; t < TILES; t++) {
        const uint32_t tbase = gbase + (t % NSLOTS) * GSLOT;

        unsigned mw0 = mrow0[t * 4];
        unsigned mw1 = mrow1[t * 4];

        // wait for this group's tile-t fill, sync the group only.
        if (t + 1 < TILES) asm volatile("cp.async.wait_group 1;" ::: "memory");
        else               asm volatile("cp.async.wait_group 0;" ::: "memory");
        BAR_GRP(wh + 1);

        if (t + 2 < TILES) {
            fill_quarter(gbase + ((t + 2) % NSLOTS) * GSLOT,
                         (t + 2) * 128 + wh * 32, ltid);
            CP_COMMIT();
        }

        // ---- S (bf16 3-pass) + softmax + bf16 P hi/lo pack
        uint32_t ph[2][4], pl[2][4];
        #pragma unroll
        for (int np = 0; np < 2; np++) {
            float s0[4] = {0.f, 0.f, 0.f, 0.f};
            float s1[4] = {0.f, 0.f, 0.f, 0.f};
            #pragma unroll
            for (int ks = 0; ks < 4; ks++) {
                uint32_t sw = SW128((np * 16 + krow_l) * 128 +
                                    (ks * 16 + kcol_l) * 2);
                uint32_t b0, b1, b2, b3;
                LDSM4(b0, b1, b2, b3, tbase + GOFF_KHI + sw);
                mma16816(s0, qh[4*ks], qh[4*ks+1], qh[4*ks+2], qh[4*ks+3], b0, b1);
                mma16816(s1, qh[4*ks], qh[4*ks+1], qh[4*ks+2], qh[4*ks+3], b2, b3);
                mma16816(s0, ql[4*ks], ql[4*ks+1], ql[4*ks+2], ql[4*ks+3], b0, b1);
                mma16816(s1, ql[4*ks], ql[4*ks+1], ql[4*ks+2], ql[4*ks+3], b2, b3);
                uint32_t c0, c1, c2, c3;
                LDSM4(c0, c1, c2, c3, tbase + GOFF_KLO + sw);
                mma16816(s0, qh[4*ks], qh[4*ks+1], qh[4*ks+2], qh[4*ks+3], c0, c1);
                mma16816(s1, qh[4*ks], qh[4*ks+1], qh[4*ks+2], qh[4*ks+3], c2, c3);
            }
            int bit = (np << 4) + 2 * tg;
            float p00 = ((mw0 >> bit) & 1u)       ? ex2f(fmaf(s0[0], sc, -mq0)) : 0.f;
            float p01 = ((mw0 >> (bit + 1)) & 1u) ? ex2f(fmaf(s0[1], sc, -mq0)) : 0.f;
            float p02 = ((mw1 >> bit) & 1u)       ? ex2f(fmaf(s0[2], sc, -mq1)) : 0.f;
            float p03 = ((mw1 >> (bit + 1)) & 1u) ? ex2f(fmaf(s0[3], sc, -mq1)) : 0.f;
            float p10 = ((mw0 >> (bit + 8)) & 1u) ? ex2f(fmaf(s1[0], sc, -mq0)) : 0.f;
            float p11 = ((mw0 >> (bit + 9)) & 1u) ? ex2f(fmaf(s1[1], sc, -mq0)) : 0.f;
            float p12 = ((mw1 >> (bit + 8)) & 1u) ? ex2f(fmaf(s1[2], sc, -mq1)) : 0.f;
            float p13 = ((mw1 >> (bit + 9)) & 1u) ? ex2f(fmaf(s1[3], sc, -mq1)) : 0.f;
            l0 += p00 + p01 + p10 + p11;
            l1 += p02 + p03 + p12 + p13;
            packbf(p00, p01, ph[np][0], pl[np][0]);
            packbf(p02, p03, ph[np][1], pl[np][1]);
            packbf(p10, p11, ph[np][2], pl[np][2]);
            packbf(p12, p13, ph[np][3], pl[np][3]);
        }

        // ---- O += P V (bf16 3-pass) over this key quarter
        #pragma unroll
        for (int ks = 0; ks < 2; ks++) {
            #pragma unroll
            for (int np = 0; np < 4; np++) {
                uint32_t sw = SW128((ks * 16 + vrow_l) * 128 +
                                    (np * 16 + vcol_l) * 2);
                uint32_t v0, v1, v2, v3;
                LDSM4T(v0, v1, v2, v3, tbase + GOFF_VHI + sw);
                mma16816(o[2*np],   ph[ks][0], ph[ks][1], ph[ks][2], ph[ks][3], v0, v1);
                mma16816(o[2*np+1], ph[ks][0], ph[ks][1], ph[ks][2], ph[ks][3], v2, v3);
                mma16816(o[2*np],   pl[ks][0], pl[ks][1], pl[ks][2], pl[ks][3], v0, v1);
                mma16816(o[2*np+1], pl[ks][0], pl[ks][1], pl[ks][2], pl[ks][3], v2, v3);
                uint32_t u0, u1, u2, u3;
                LDSM4T(u0, u1, u2, u3, tbase + GOFF_VLO + sw);
                mma16816(o[2*np],   ph[ks][0], ph[ks][1], ph[ks][2], ph[ks][3], u0, u1);
                mma16816(o[2*np+1], ph[ks][0], ph[ks][1], ph[ks][2], ph[ks][3], u2, u3);
            }
        }
    }

    // ---- combine 4 key quarters: wh>0 dump partials, wh==0 finalizes.
    __syncthreads();
    float* cmb = (float*)smem;   // 3*128*34 floats = 52KB (slots free now)
    if (wh > 0) {
        float* dst = cmb + ((wh - 1) * 128 + wq * 32 + lane) * 34;
        #pragma unroll
        for (int i = 0; i < 8; i++)
            #pragma unroll
            for (int j = 0; j < 4; j++) dst[i * 4 + j] = o[i][j];
        dst[32] = l0;
        dst[33] = l1;
    }
    __syncthreads();
    if (wh == 0) {
        #pragma unroll
        for (int q = 0; q < 3; q++) {
            const float* src = cmb + (q * 128 + wq * 32 + lane) * 34;
            #pragma unroll
            for (int i = 0; i < 8; i++)
                #pragma unroll
                for (int j = 0; j < 4; j++) o[i][j] += src[i * 4 + j];
            l0 += src[32];
            l1 += src[33];
        }
        l0 += __shfl_xor_sync(0xffffffffu, l0, 1);
        l0 += __shfl_xor_sync(0xffffffffu, l0, 2);
        l1 += __shfl_xor_sync(0xffffffffu, l1, 1);
        l1 += __shfl_xor_sync(0xffffffffu, l1, 2);
        float inv0 = 1.f / l0, inv1 = 1.f / l1;

        int gr0 = qbase + q0 + g, gr1 = gr0 + 8;
        #pragma unroll
        for (int nt = 0; nt < 8; nt++) {
            float x0 = o[nt][0] * inv0; x0 = (x0 > 0.f) ? x0 : expm1f(x0);
            float x1 = o[nt][1] * inv0; x1 = (x1 > 0.f) ? x1 : expm1f(x1);
            float x2 = o[nt][2] * inv1; x2 = (x2 > 0.f) ? x2 : expm1f(x2);
            float x3 = o[nt][3] * inv1; x3 = (x3 > 0.f) ? x3 : expm1f(x3);
            *(float2*)(out + (long)gr0 * DD + nt * 8 + 2 * tg) = make_float2(x0, x1);
            *(float2*)(out + (long)gr1 * DD + nt * 8 + 2 * tg) = make_float2(x2, x3);
        }
    }
}

namespace {
struct AttrInit {
    AttrInit() {
        cudaFuncSetAttribute(attn_kernel,
                             cudaFuncAttributeMaxDynamicSharedMemorySize,
                             SMEM_ATTN);
    }
} attr_init_;
}

extern "C" void kernel_launch(void* const* d_in, const int* in_sizes, int n_in,
                              void* d_out, int out_size) {
    const float* inp = nullptr;
    const int*   adj = nullptr;
    const float* kW  = nullptr;
    const float* vW  = nullptr;
    for (int i = 0; i < n_in; i++) {
        long sz = in_sizes[i];
        if (sz == (long)NN * DIN)      inp = (const float*)d_in[i];
        else if (sz == (long)NN * NN)  adj = (const int*)d_in[i];
        else if (sz == (long)DIN * DD) { if (!kW) kW = (const float*)d_in[i];
                                         else     vW = (const float*)d_in[i]; }
    }
    float* out = (float*)d_out;

    cudaFuncSetAttribute(attn_kernel,
                         cudaFuncAttributeMaxDynamicSharedMemorySize, SMEM_ATTN);

    prep_kernel<<<PROJ_CTAS + MASK_CTAS, 256>>>(inp, kW, vW, adj);
    attn_kernel<<<NN / 64, 512, SMEM_ATTN>>>(out);
}